// round 3
// baseline (speedup 1.0000x reference)
#include <cuda_runtime.h>
#include <cuda_bf16.h>

// CliffordLayerNorm, two-pass variant with exact work partition:
//   pass 1: stream x -> grade sums S/Q (no values held in registers)
//   shuffle-XOR grade-polynomial butterfly -> per-grade affine coeffs
//   pass 2: re-load x (L1/L2-resident) -> single FMA -> streaming store
// 8 lanes per MV, warp covers 4 MVs (4KB) per group; each warp owns a
// contiguous run of groups (zero remainder when sizes divide evenly).

#define NG 9
#define CEPS 1e-5f

__global__ void __launch_bounds__(256, 3)
clifford_ln_kernel(const float* __restrict__ x,
                   const float* __restrict__ weight,
                   const float* __restrict__ bias,
                   float* __restrict__ out,
                   int num_groups,      // groups of 1024 floats (4 MVs)
                   int groups_per_warp) // contiguous groups per warp
{
    const int lane = threadIdx.x & 31;
    const int wid_global = blockIdx.x * (blockDim.x >> 5) + (threadIdx.x >> 5);
    const int sub = lane & 7;     // covers element bits 2,3,4
    const int mv  = lane >> 3;    // which of 4 MVs in the group
    const int p   = __popc(sub);  // relative grade base, 0..3

    // per-grade reciprocal counts C(8,g) = 1,8,28,56,70,56,28,8,1
    const float rc[NG] = {1.0f, 1.0f/8.0f, 1.0f/28.0f, 1.0f/56.0f, 1.0f/70.0f,
                          1.0f/56.0f, 1.0f/28.0f, 1.0f/8.0f, 1.0f};

    float wgt[NG], bs[NG];
#pragma unroll
    for (int g = 0; g < NG; ++g) {
        wgt[g] = __ldg(weight + g);
        bs[g]  = __ldg(bias + g);
    }

    const int grp_base = wid_global * groups_per_warp;

#pragma unroll 1
    for (int i = 0; i < groups_per_warp; ++i) {
        const int grp = grp_base + i;
        if (grp >= num_groups) break;

        const float4* __restrict__ xin =
            reinterpret_cast<const float4*>(x) + (size_t)grp * 256 + mv * 64 + sub;
        float4* __restrict__ xout =
            reinterpret_cast<float4*>(out) + (size_t)grp * 256 + mv * 64 + sub;

        // ---- Pass 1: stream loads into grade-relative partial sums ----
        // t = popc(k)+popc(j) in 0..5.
        float S[NG], Q[NG];
#pragma unroll
        for (int t = 0; t < NG; ++t) { S[t] = 0.0f; Q[t] = 0.0f; }
#pragma unroll
        for (int k = 0; k < 8; ++k) {
            const int pk = __popc(k);          // compile-time after unroll
            const float4 v = xin[k * 8];
            S[pk + 0] += v.x;  Q[pk + 0] = fmaf(v.x, v.x, Q[pk + 0]);
            S[pk + 1] += v.y;  Q[pk + 1] = fmaf(v.y, v.y, Q[pk + 1]);
            S[pk + 1] += v.z;  Q[pk + 1] = fmaf(v.z, v.z, Q[pk + 1]);
            S[pk + 2] += v.w;  Q[pk + 2] = fmaf(v.w, v.w, Q[pk + 2]);
        }

        // ---- Butterfly merge over lane bits 0..2 (sub). 6 -> 7 -> 8 -> 9 ----
#pragma unroll
        for (int b = 0; b < 3; ++b) {
            const int n = 6 + b;               // current valid length
            const bool up = (sub >> b) & 1;
            float Sp[NG], Qp[NG];
#pragma unroll
            for (int t = 0; t < NG; ++t) {
                if (t < n) {
                    Sp[t] = __shfl_xor_sync(0xffffffffu, S[t], 1 << b);
                    Qp[t] = __shfl_xor_sync(0xffffffffu, Q[t], 1 << b);
                }
            }
            float Sn[NG], Qn[NG];
#pragma unroll
            for (int t = 0; t < NG; ++t) {
                if (t <= n) {
                    float lo_s = (t < n) ? (up ? Sp[t] : S[t]) : 0.0f;
                    float hi_s = (t > 0) ? (up ? S[t - 1] : Sp[t - 1]) : 0.0f;
                    Sn[t] = lo_s + hi_s;
                    float lo_q = (t < n) ? (up ? Qp[t] : Q[t]) : 0.0f;
                    float hi_q = (t > 0) ? (up ? Q[t - 1] : Qp[t - 1]) : 0.0f;
                    Qn[t] = lo_q + hi_q;
                }
            }
#pragma unroll
            for (int t = 0; t < NG; ++t) {
                if (t <= n) { S[t] = Sn[t]; Q[t] = Qn[t]; }
            }
        }

        // ---- Per-grade affine coefficients; compress to this lane's 6 ----
        float At[6], Bt[6];
#pragma unroll
        for (int g = 0; g < NG; ++g) {
            float m   = S[g] * rc[g];
            float var = fmaf(Q[g], rc[g], -m * m);
            float inv = rsqrtf(var + CEPS);
            float a   = inv * wgt[g];
            float b   = fmaf(-m, a, bs[g]);
            // lane needs grades p..p+5 -> slot t = g - p
#pragma unroll
            for (int t = 0; t < 6; ++t) {
                if (g - t == 0 ? (p == 0) : (g - t == 1 ? (p == 1) :
                    (g - t == 2 ? (p == 2) : (g - t == 3 && p == 3)))) {
                    At[t] = a; Bt[t] = b;
                }
            }
        }

        // ---- Pass 2: reload x (cache hit), FMA, streaming store ----
        // asm volatile loads prevent CSE with pass-1 loads.
#pragma unroll
        for (int k = 0; k < 8; ++k) {
            const int pk = __popc(k);
            const float4* addr = xin + k * 8;
            float vx, vy, vz, vw;
            asm volatile("ld.global.nc.v4.f32 {%0,%1,%2,%3}, [%4];"
                         : "=f"(vx), "=f"(vy), "=f"(vz), "=f"(vw)
                         : "l"(addr));
            float4 o;
            o.x = fmaf(vx, At[pk + 0], Bt[pk + 0]);
            o.y = fmaf(vy, At[pk + 1], Bt[pk + 1]);
            o.z = fmaf(vz, At[pk + 1], Bt[pk + 1]);
            o.w = fmaf(vw, At[pk + 2], Bt[pk + 2]);
            __stcs(xout + k * 8, o);           // evict-first: write-once output
        }
    }
}

extern "C" void kernel_launch(void* const* d_in, const int* in_sizes, int n_in,
                              void* d_out, int out_size)
{
    const float* x      = (const float*)d_in[0];
    const float* weight = (const float*)d_in[1];
    const float* bias   = (const float*)d_in[2];
    float* out          = (float*)d_out;

    const int num_groups = in_sizes[0] / 1024;   // 4 MVs (1024 floats) per group

    // Exact partition: 8 warps/CTA, groups_per_warp chosen so the division is
    // remainder-free when possible (65536 groups -> 1024 CTAs x 8 warps x 8).
    int gpw = 8;
    int warps_needed = (num_groups + gpw - 1) / gpw;
    int blocks = (warps_needed + 7) / 8;
    clifford_ln_kernel<<<blocks, 256>>>(x, weight, bias, out, num_groups, gpw);
}

// round 4
// speedup vs baseline: 1.0326x; 1.0326x over previous
#include <cuda_runtime.h>
#include <cuda_bf16.h>

// CliffordLayerNorm, two-pass variant (R2 structure) + persistent grid:
//   pass 1: stream x -> grade sums S/Q (no values held in registers)
//   shuffle-XOR grade-polynomial butterfly -> per-grade affine coeffs
//   pass 2: re-load x (L1/L2-resident) -> single FMA -> plain store
// 8 lanes per MV, warp covers 4 MVs (4KB) per group, grid-stride over groups.
// Grid = 148 SMs x 3 resident CTAs: single wave, no wave transitions,
// fine-grained (~18 iter/warp) load balance.

#define NG 9
#define CEPS 1e-5f

__global__ void __launch_bounds__(256, 3)
clifford_ln_kernel(const float* __restrict__ x,
                   const float* __restrict__ weight,
                   const float* __restrict__ bias,
                   float* __restrict__ out,
                   int num_groups)   // groups of 1024 floats (4 MVs)
{
    const int lane = threadIdx.x & 31;
    const int wid_global = blockIdx.x * (blockDim.x >> 5) + (threadIdx.x >> 5);
    const int nwarps = gridDim.x * (blockDim.x >> 5);
    const int sub = lane & 7;     // covers element bits 2,3,4
    const int mv  = lane >> 3;    // which of 4 MVs in the group
    const int p   = __popc(sub);  // relative grade base, 0..3

    // per-grade reciprocal counts C(8,g) = 1,8,28,56,70,56,28,8,1
    const float rc[NG] = {1.0f, 1.0f/8.0f, 1.0f/28.0f, 1.0f/56.0f, 1.0f/70.0f,
                          1.0f/56.0f, 1.0f/28.0f, 1.0f/8.0f, 1.0f};

    float wgt[NG], bs[NG];
#pragma unroll
    for (int g = 0; g < NG; ++g) {
        wgt[g] = __ldg(weight + g);
        bs[g]  = __ldg(bias + g);
    }

    for (int grp = wid_global; grp < num_groups; grp += nwarps) {
        const float4* __restrict__ xin =
            reinterpret_cast<const float4*>(x) + (size_t)grp * 256 + mv * 64 + sub;
        float4* __restrict__ xout =
            reinterpret_cast<float4*>(out) + (size_t)grp * 256 + mv * 64 + sub;

        // ---- Pass 1: stream loads into grade-relative partial sums ----
        // t = popc(k)+popc(j) in 0..5.
        float S[NG], Q[NG];
#pragma unroll
        for (int t = 0; t < NG; ++t) { S[t] = 0.0f; Q[t] = 0.0f; }
#pragma unroll
        for (int k = 0; k < 8; ++k) {
            const int pk = __popc(k);          // compile-time after unroll
            const float4 v = xin[k * 8];
            S[pk + 0] += v.x;  Q[pk + 0] = fmaf(v.x, v.x, Q[pk + 0]);
            S[pk + 1] += v.y;  Q[pk + 1] = fmaf(v.y, v.y, Q[pk + 1]);
            S[pk + 1] += v.z;  Q[pk + 1] = fmaf(v.z, v.z, Q[pk + 1]);
            S[pk + 2] += v.w;  Q[pk + 2] = fmaf(v.w, v.w, Q[pk + 2]);
        }

        // ---- Butterfly merge over lane bits 0..2 (sub). 6 -> 7 -> 8 -> 9 ----
#pragma unroll
        for (int b = 0; b < 3; ++b) {
            const int n = 6 + b;               // current valid length
            const bool up = (sub >> b) & 1;
            float Sp[NG], Qp[NG];
#pragma unroll
            for (int t = 0; t < NG; ++t) {
                if (t < n) {
                    Sp[t] = __shfl_xor_sync(0xffffffffu, S[t], 1 << b);
                    Qp[t] = __shfl_xor_sync(0xffffffffu, Q[t], 1 << b);
                }
            }
            float Sn[NG], Qn[NG];
#pragma unroll
            for (int t = 0; t < NG; ++t) {
                if (t <= n) {
                    float lo_s = (t < n) ? (up ? Sp[t] : S[t]) : 0.0f;
                    float hi_s = (t > 0) ? (up ? S[t - 1] : Sp[t - 1]) : 0.0f;
                    Sn[t] = lo_s + hi_s;
                    float lo_q = (t < n) ? (up ? Qp[t] : Q[t]) : 0.0f;
                    float hi_q = (t > 0) ? (up ? Q[t - 1] : Qp[t - 1]) : 0.0f;
                    Qn[t] = lo_q + hi_q;
                }
            }
#pragma unroll
            for (int t = 0; t < NG; ++t) {
                if (t <= n) { S[t] = Sn[t]; Q[t] = Qn[t]; }
            }
        }

        // ---- Per-grade affine coefficients; compress to this lane's 6 ----
        float At[6], Bt[6];
#pragma unroll
        for (int g = 0; g < NG; ++g) {
            float m   = S[g] * rc[g];
            float var = fmaf(Q[g], rc[g], -m * m);
            float inv = rsqrtf(var + CEPS);
            float a   = inv * wgt[g];
            float b   = fmaf(-m, a, bs[g]);
            // lane needs grades p..p+5 -> slot t = g - p
#pragma unroll
            for (int t = 0; t < 6; ++t) {
                if (g - t == 0 ? (p == 0) : (g - t == 1 ? (p == 1) :
                    (g - t == 2 ? (p == 2) : (g - t == 3 && p == 3)))) {
                    At[t] = a; Bt[t] = b;
                }
            }
        }

        // ---- Pass 2: reload x (cache hit), FMA, plain store ----
        // asm volatile loads prevent CSE with pass-1 loads.
#pragma unroll
        for (int k = 0; k < 8; ++k) {
            const int pk = __popc(k);
            const float4* addr = xin + k * 8;
            float vx, vy, vz, vw;
            asm volatile("ld.global.nc.v4.f32 {%0,%1,%2,%3}, [%4];"
                         : "=f"(vx), "=f"(vy), "=f"(vz), "=f"(vw)
                         : "l"(addr));
            float4 o;
            o.x = fmaf(vx, At[pk + 0], Bt[pk + 0]);
            o.y = fmaf(vy, At[pk + 1], Bt[pk + 1]);
            o.z = fmaf(vz, At[pk + 1], Bt[pk + 1]);
            o.w = fmaf(vw, At[pk + 2], Bt[pk + 2]);
            xout[k * 8] = o;
        }
    }
}

extern "C" void kernel_launch(void* const* d_in, const int* in_sizes, int n_in,
                              void* d_out, int out_size)
{
    const float* x      = (const float*)d_in[0];
    const float* weight = (const float*)d_in[1];
    const float* bias   = (const float*)d_in[2];
    float* out          = (float*)d_out;

    const int num_groups = in_sizes[0] / 1024;   // 4 MVs (1024 floats) per group

    // Persistent grid: exactly one wave (148 SMs x 3 CTAs), grid-stride loop.
    const int threads = 256;
    const int blocks  = 444;
    clifford_ln_kernel<<<blocks, threads>>>(x, weight, bias, out, num_groups);
}

// round 5
// speedup vs baseline: 1.1822x; 1.1449x over previous
#include <cuda_runtime.h>
#include <cuda_bf16.h>

// CliffordLayerNorm, two-pass variant (R2 structure), fine-grained grid:
//   pass 1: stream x -> grade sums S/Q (no values held in registers)
//   shuffle-XOR grade-polynomial butterfly -> per-grade affine coeffs
//   pass 2: re-load x (L1-resident) -> single FMA -> plain store
// 8 lanes per MV, warp covers 4 MVs (4KB) per group.
// Grid sized so each warp handles EXACTLY 2 groups (remainder-free), ~14
// waves: HW CTA scheduler dynamically backfills slow SMs (high-MLP_p1
// spread regime), minimizing the drain tail.

#define NG 9
#define CEPS 1e-5f

__global__ void __launch_bounds__(256, 3)
clifford_ln_kernel(const float* __restrict__ x,
                   const float* __restrict__ weight,
                   const float* __restrict__ bias,
                   float* __restrict__ out,
                   int num_groups)   // groups of 1024 floats (4 MVs)
{
    const int lane = threadIdx.x & 31;
    const int wid_global = blockIdx.x * (blockDim.x >> 5) + (threadIdx.x >> 5);
    const int nwarps = gridDim.x * (blockDim.x >> 5);
    const int sub = lane & 7;     // covers element bits 2,3,4
    const int mv  = lane >> 3;    // which of 4 MVs in the group
    const int p   = __popc(sub);  // relative grade base, 0..3

    // per-grade reciprocal counts C(8,g) = 1,8,28,56,70,56,28,8,1
    const float rc[NG] = {1.0f, 1.0f/8.0f, 1.0f/28.0f, 1.0f/56.0f, 1.0f/70.0f,
                          1.0f/56.0f, 1.0f/28.0f, 1.0f/8.0f, 1.0f};

    float wgt[NG], bs[NG];
#pragma unroll
    for (int g = 0; g < NG; ++g) {
        wgt[g] = __ldg(weight + g);
        bs[g]  = __ldg(bias + g);
    }

    for (int grp = wid_global; grp < num_groups; grp += nwarps) {
        const float4* __restrict__ xin =
            reinterpret_cast<const float4*>(x) + (size_t)grp * 256 + mv * 64 + sub;
        float4* __restrict__ xout =
            reinterpret_cast<float4*>(out) + (size_t)grp * 256 + mv * 64 + sub;

        // ---- Pass 1: stream loads into grade-relative partial sums ----
        // t = popc(k)+popc(j) in 0..5.
        float S[NG], Q[NG];
#pragma unroll
        for (int t = 0; t < NG; ++t) { S[t] = 0.0f; Q[t] = 0.0f; }
#pragma unroll
        for (int k = 0; k < 8; ++k) {
            const int pk = __popc(k);          // compile-time after unroll
            const float4 v = xin[k * 8];
            S[pk + 0] += v.x;  Q[pk + 0] = fmaf(v.x, v.x, Q[pk + 0]);
            S[pk + 1] += v.y;  Q[pk + 1] = fmaf(v.y, v.y, Q[pk + 1]);
            S[pk + 1] += v.z;  Q[pk + 1] = fmaf(v.z, v.z, Q[pk + 1]);
            S[pk + 2] += v.w;  Q[pk + 2] = fmaf(v.w, v.w, Q[pk + 2]);
        }

        // ---- Butterfly merge over lane bits 0..2 (sub). 6 -> 7 -> 8 -> 9 ----
#pragma unroll
        for (int b = 0; b < 3; ++b) {
            const int n = 6 + b;               // current valid length
            const bool up = (sub >> b) & 1;
            float Sp[NG], Qp[NG];
#pragma unroll
            for (int t = 0; t < NG; ++t) {
                if (t < n) {
                    Sp[t] = __shfl_xor_sync(0xffffffffu, S[t], 1 << b);
                    Qp[t] = __shfl_xor_sync(0xffffffffu, Q[t], 1 << b);
                }
            }
            float Sn[NG], Qn[NG];
#pragma unroll
            for (int t = 0; t < NG; ++t) {
                if (t <= n) {
                    float lo_s = (t < n) ? (up ? Sp[t] : S[t]) : 0.0f;
                    float hi_s = (t > 0) ? (up ? S[t - 1] : Sp[t - 1]) : 0.0f;
                    Sn[t] = lo_s + hi_s;
                    float lo_q = (t < n) ? (up ? Qp[t] : Q[t]) : 0.0f;
                    float hi_q = (t > 0) ? (up ? Q[t - 1] : Qp[t - 1]) : 0.0f;
                    Qn[t] = lo_q + hi_q;
                }
            }
#pragma unroll
            for (int t = 0; t < NG; ++t) {
                if (t <= n) { S[t] = Sn[t]; Q[t] = Qn[t]; }
            }
        }

        // ---- Per-grade affine coefficients; compress to this lane's 6 ----
        float At[6], Bt[6];
#pragma unroll
        for (int g = 0; g < NG; ++g) {
            float m   = S[g] * rc[g];
            float var = fmaf(Q[g], rc[g], -m * m);
            float inv = rsqrtf(var + CEPS);
            float a   = inv * wgt[g];
            float b   = fmaf(-m, a, bs[g]);
            // lane needs grades p..p+5 -> slot t = g - p
#pragma unroll
            for (int t = 0; t < 6; ++t) {
                if (g - t == 0 ? (p == 0) : (g - t == 1 ? (p == 1) :
                    (g - t == 2 ? (p == 2) : (g - t == 3 && p == 3)))) {
                    At[t] = a; Bt[t] = b;
                }
            }
        }

        // ---- Pass 2: reload x (cache hit), FMA, plain store ----
        // asm volatile loads prevent CSE with pass-1 loads.
#pragma unroll
        for (int k = 0; k < 8; ++k) {
            const int pk = __popc(k);
            const float4* addr = xin + k * 8;
            float vx, vy, vz, vw;
            asm volatile("ld.global.nc.v4.f32 {%0,%1,%2,%3}, [%4];"
                         : "=f"(vx), "=f"(vy), "=f"(vz), "=f"(vw)
                         : "l"(addr));
            float4 o;
            o.x = fmaf(vx, At[pk + 0], Bt[pk + 0]);
            o.y = fmaf(vy, At[pk + 1], Bt[pk + 1]);
            o.z = fmaf(vz, At[pk + 1], Bt[pk + 1]);
            o.w = fmaf(vw, At[pk + 2], Bt[pk + 2]);
            xout[k * 8] = o;
        }
    }
}

extern "C" void kernel_launch(void* const* d_in, const int* in_sizes, int n_in,
                              void* d_out, int out_size)
{
    const float* x      = (const float*)d_in[0];
    const float* weight = (const float*)d_in[1];
    const float* bias   = (const float*)d_in[2];
    float* out          = (float*)d_out;

    const int num_groups = in_sizes[0] / 1024;   // 4 MVs (1024 floats) per group

    // Fine-grained grid: exactly 2 groups per warp when sizes divide evenly
    // (65536 groups -> 4096 CTAs x 8 warps x 2). Many waves -> HW dynamic
    // CTA backfill absorbs per-SM speed variance.
    const int threads = 256;
    int warps_needed = (num_groups + 1) / 2;
    int blocks = (warps_needed + 7) / 8;
    clifford_ln_kernel<<<blocks, threads>>>(x, weight, bias, out, num_groups);
}

// round 6
// speedup vs baseline: 1.1938x; 1.0098x over previous
#include <cuda_runtime.h>
#include <cuda_bf16.h>

// CliffordLayerNorm, two-pass variant, ONE group (4 MVs, 4KB) per warp:
//   pass 1: stream x -> grade sums S/Q (no values held in registers)
//   shuffle-XOR grade-polynomial butterfly -> per-grade affine coeffs
//   pass 2: re-load x (L1-resident) -> single FMA -> plain store
// No grid-stride loop: each warp processes exactly one group and exits.
// 8192 CTAs (~18 waves) -> HW CLC dynamically backfills slow SMs, minimal
// tail, registers freed at warp exit pipeline the next CTA's load burst.

#define NG 9
#define CEPS 1e-5f

__global__ void __launch_bounds__(256, 3)
clifford_ln_kernel(const float* __restrict__ x,
                   const float* __restrict__ weight,
                   const float* __restrict__ bias,
                   float* __restrict__ out,
                   int num_groups)   // groups of 1024 floats (4 MVs)
{
    const int lane = threadIdx.x & 31;
    const int grp = blockIdx.x * (blockDim.x >> 5) + (threadIdx.x >> 5);
    if (grp >= num_groups) return;

    const int sub = lane & 7;     // covers element bits 2,3,4
    const int mv  = lane >> 3;    // which of 4 MVs in the group
    const int p   = __popc(sub);  // relative grade base, 0..3

    // per-grade reciprocal counts C(8,g) = 1,8,28,56,70,56,28,8,1
    const float rc[NG] = {1.0f, 1.0f/8.0f, 1.0f/28.0f, 1.0f/56.0f, 1.0f/70.0f,
                          1.0f/56.0f, 1.0f/28.0f, 1.0f/8.0f, 1.0f};

    const float4* __restrict__ xin =
        reinterpret_cast<const float4*>(x) + (size_t)grp * 256 + mv * 64 + sub;
    float4* __restrict__ xout =
        reinterpret_cast<float4*>(out) + (size_t)grp * 256 + mv * 64 + sub;

    // ---- Pass 1: stream loads into grade-relative partial sums ----
    // t = popc(k)+popc(j) in 0..5.
    float S[NG], Q[NG];
#pragma unroll
    for (int t = 0; t < NG; ++t) { S[t] = 0.0f; Q[t] = 0.0f; }
#pragma unroll
    for (int k = 0; k < 8; ++k) {
        const int pk = __popc(k);          // compile-time after unroll
        const float4 v = xin[k * 8];
        S[pk + 0] += v.x;  Q[pk + 0] = fmaf(v.x, v.x, Q[pk + 0]);
        S[pk + 1] += v.y;  Q[pk + 1] = fmaf(v.y, v.y, Q[pk + 1]);
        S[pk + 1] += v.z;  Q[pk + 1] = fmaf(v.z, v.z, Q[pk + 1]);
        S[pk + 2] += v.w;  Q[pk + 2] = fmaf(v.w, v.w, Q[pk + 2]);
    }

    // ---- Butterfly merge over lane bits 0..2 (sub). 6 -> 7 -> 8 -> 9 ----
#pragma unroll
    for (int b = 0; b < 3; ++b) {
        const int n = 6 + b;               // current valid length
        const bool up = (sub >> b) & 1;
        float Sp[NG], Qp[NG];
#pragma unroll
        for (int t = 0; t < NG; ++t) {
            if (t < n) {
                Sp[t] = __shfl_xor_sync(0xffffffffu, S[t], 1 << b);
                Qp[t] = __shfl_xor_sync(0xffffffffu, Q[t], 1 << b);
            }
        }
        float Sn[NG], Qn[NG];
#pragma unroll
        for (int t = 0; t < NG; ++t) {
            if (t <= n) {
                float lo_s = (t < n) ? (up ? Sp[t] : S[t]) : 0.0f;
                float hi_s = (t > 0) ? (up ? S[t - 1] : Sp[t - 1]) : 0.0f;
                Sn[t] = lo_s + hi_s;
                float lo_q = (t < n) ? (up ? Qp[t] : Q[t]) : 0.0f;
                float hi_q = (t > 0) ? (up ? Q[t - 1] : Qp[t - 1]) : 0.0f;
                Qn[t] = lo_q + hi_q;
            }
        }
#pragma unroll
        for (int t = 0; t < NG; ++t) {
            if (t <= n) { S[t] = Sn[t]; Q[t] = Qn[t]; }
        }
    }

    // ---- Per-grade affine coefficients; compress to this lane's 6 ----
    float At[6], Bt[6];
#pragma unroll
    for (int g = 0; g < NG; ++g) {
        float m   = S[g] * rc[g];
        float var = fmaf(Q[g], rc[g], -m * m);
        float inv = rsqrtf(var + CEPS);
        float a   = inv * __ldg(weight + g);
        float b   = fmaf(-m, a, __ldg(bias + g));
        // lane needs grades p..p+5 -> slot t = g - p
#pragma unroll
        for (int t = 0; t < 6; ++t) {
            if (g - t == 0 ? (p == 0) : (g - t == 1 ? (p == 1) :
                (g - t == 2 ? (p == 2) : (g - t == 3 && p == 3)))) {
                At[t] = a; Bt[t] = b;
            }
        }
    }

    // ---- Pass 2: reload x (cache hit), FMA, plain store ----
    // asm volatile loads prevent CSE with pass-1 loads.
#pragma unroll
    for (int k = 0; k < 8; ++k) {
        const int pk = __popc(k);
        const float4* addr = xin + k * 8;
        float vx, vy, vz, vw;
        asm volatile("ld.global.nc.v4.f32 {%0,%1,%2,%3}, [%4];"
                     : "=f"(vx), "=f"(vy), "=f"(vz), "=f"(vw)
                     : "l"(addr));
        float4 o;
        o.x = fmaf(vx, At[pk + 0], Bt[pk + 0]);
        o.y = fmaf(vy, At[pk + 1], Bt[pk + 1]);
        o.z = fmaf(vz, At[pk + 1], Bt[pk + 1]);
        o.w = fmaf(vw, At[pk + 2], Bt[pk + 2]);
        xout[k * 8] = o;
    }
}

extern "C" void kernel_launch(void* const* d_in, const int* in_sizes, int n_in,
                              void* d_out, int out_size)
{
    const float* x      = (const float*)d_in[0];
    const float* weight = (const float*)d_in[1];
    const float* bias   = (const float*)d_in[2];
    float* out          = (float*)d_out;

    const int num_groups = in_sizes[0] / 1024;   // 4 MVs (1024 floats) per group

    // One group per warp, 8 warps per CTA -> num_groups/8 CTAs (~18 waves).
    const int threads = 256;
    int blocks = (num_groups + 7) / 8;
    clifford_ln_kernel<<<blocks, threads>>>(x, weight, bias, out, num_groups);
}